// round 13
// baseline (speedup 1.0000x reference)
#include <cuda_runtime.h>
#include <cuda_bf16.h>
#include <cuda_fp16.h>
#include <cstdint>
#include <math.h>

#define NROWS 8192
#define DDIM  1024
#define TMR   128                     // tile rows
#define TNC   256                     // tile cols
#define NIB   (NROWS / TMR)           // 64
#define NJB   (NROWS / TNC)           // 32
#define NTILES 1056                   // sum_{ib<64} (32 - (ib>>1))
#define NKT   (DDIM / 32)             // 32 k-slices of 32
#define NIT   (NKT / 2)               // 16 mainloop iterations (BK=64)
#define PLANE ((size_t)NROWS * 32)    // bytes per k-slice plane
#define F8SCALE 16.0f
#define SCALE (14.285714285714285f / (F8SCALE * F8SCALE))

#define STAGE  24576                  // 8KB A + 16KB B (2 k-planes each)
#define SMEM_DYN (4 * STAGE)          // 98304

// ---------------- device scratch ----------------
__device__ uint8_t g_p8[(size_t)NKT * PLANE];
__device__ float g_rowsum[NROWS];
__device__ float g_pos[NROWS];

// ---------------- PTX helpers ----------------
__device__ __forceinline__ uint32_t smem_u32(const void* p) {
    return (uint32_t)__cvta_generic_to_shared(p);
}
__device__ __forceinline__ void cp_async_16(uint32_t dst, const void* src) {
    asm volatile("cp.async.cg.shared.global [%0], [%1], 16;" :: "r"(dst), "l"(src) : "memory");
}
__device__ __forceinline__ void cp_commit() {
    asm volatile("cp.async.commit_group;" ::: "memory");
}
__device__ __forceinline__ void cp_wait2() {
    asm volatile("cp.async.wait_group 2;" ::: "memory");
}
__device__ __forceinline__ void lds64(uint32_t& r0, uint32_t& r1, uint32_t addr) {
    asm volatile("ld.shared.v2.u32 {%0,%1}, [%2];" : "=r"(r0), "=r"(r1) : "r"(addr));
}
// fp8 x fp8 -> f16 accumulator (half2 pair)
__device__ __forceinline__ void mma_e4m3_h(uint32_t& d0, uint32_t& d1,
                                           uint32_t a0, uint32_t a1, uint32_t a2, uint32_t a3,
                                           uint32_t b0, uint32_t b1) {
    asm volatile("mma.sync.aligned.m16n8k32.row.col.f16.e4m3.e4m3.f16 "
                 "{%0,%1}, {%2,%3,%4,%5}, {%6,%7}, {%0,%1};"
                 : "+r"(d0), "+r"(d1)
                 : "r"(a0), "r"(a1), "r"(a2), "r"(a3), "r"(b0), "r"(b1));
}
__device__ __forceinline__ uint16_t f2e4m3(float hi, float lo) {
    uint16_t r;
    asm("cvt.rn.satfinite.e4m3x2.f32 %0, %1, %2;" : "=h"(r) : "f"(hi), "f"(lo));
    return r;
}

// ---------------- kernel 1: normalize + pack (warp-per-row, single pass) ----------------
__global__ __launch_bounds__(256) void norm_kernel(const float* __restrict__ z,
                                                   float* __restrict__ out) {
    int warp = (blockIdx.x * 256 + threadIdx.x) >> 5;
    int lane = threadIdx.x & 31;
    int row = warp;
    const float4* zr4 = (const float4*)(z + (size_t)row * DDIM);

    float4 v[8];
    float ss = 0.f;
    #pragma unroll
    for (int i = 0; i < 8; i++) {
        v[i] = zr4[lane + 32 * i];
        ss = fmaf(v[i].x, v[i].x, ss);
        ss = fmaf(v[i].y, v[i].y, ss);
        ss = fmaf(v[i].z, v[i].z, ss);
        ss = fmaf(v[i].w, v[i].w, ss);
    }
    #pragma unroll
    for (int o = 16; o; o >>= 1) ss += __shfl_xor_sync(0xffffffffu, ss, o);
    float nrm = fmaxf(sqrtf(ss), 1e-8f);
    float inv = (1.f / nrm) * F8SCALE;

    int natom = row >> 3, gb = row & 7;
    #pragma unroll
    for (int i = 0; i < 8; i++) {
        int q = lane + 32 * i;
        uint32_t word = (uint32_t)f2e4m3(v[i].y * inv, v[i].x * inv)
                      | ((uint32_t)f2e4m3(v[i].w * inv, v[i].z * inv) << 16);
        int kt = q >> 3, tig = q & 3, half = (q >> 2) & 1;
        size_t boff = (size_t)kt * PLANE + (size_t)natom * 256
                    + (size_t)(gb * 4 + tig) * 8 + (size_t)half * 4;
        *(uint32_t*)(g_p8 + boff) = word;
    }
    if (lane == 0) g_rowsum[row] = 0.f;
    if (blockIdx.x == 0 && threadIdx.x == 0) out[0] = 0.f;
}

// ---------------- kernel 2: 128x256 band-triangular gram, f16 acc ----------------
__global__ __launch_bounds__(256, 2) void gram_kernel() {
    extern __shared__ uint8_t dsmem[];
    __shared__ float s_row[TMR];
    __shared__ float s_col[TNC];

    int tid = threadIdx.x;
    int lane = tid & 31, w = tid >> 5;
    int wm = w >> 2, wn = w & 3;   // warp tile: 64 rows x 64 cols

    uint32_t sbase = smem_u32(dsmem);

    // band-triangular decode: jb in [ib>>1, NJB)
    int t = blockIdx.x, ib = 0;
    for (;;) { int cnt = NJB - (ib >> 1); if (t < cnt) break; t -= cnt; ib++; }
    int jb = (ib >> 1) + t;
    bool band = (jb == (ib >> 1));
    bool posband = (jb == (ib >> 1) + NJB / 2);

    if (tid < TMR) s_row[tid] = 0.f;
    s_col[tid] = 0.f;

    uint32_t wdst = sbase + (uint32_t)tid * 16;
    const uint8_t* asrc = g_p8 + (size_t)ib * 4096 + tid * 16;   // A block: 16 atoms/plane
    const uint8_t* bsrc = g_p8 + (size_t)jb * 8192 + tid * 16;   // B block: 32 atoms/plane
    uint32_t a_rd = sbase + (uint32_t)((wm * 8) * 256 + lane * 8);
    uint32_t b_rd = sbase + (uint32_t)(8192 + (wn * 8) * 256 + lane * 8);

    uint32_t acc[4][8][2];   // f16x2 accumulators
    #pragma unroll
    for (int mt = 0; mt < 4; mt++)
        #pragma unroll
        for (int nt = 0; nt < 8; nt++) { acc[mt][nt][0] = 0u; acc[mt][nt][1] = 0u; }

    // prologue: 3 stages (stage s covers planes 2s, 2s+1)
    #pragma unroll
    for (int s = 0; s < 3; s++) {
        uint32_t sb = wdst + (uint32_t)(s * STAGE);
        const uint8_t* pa = asrc + (size_t)(2 * s) * PLANE;
        const uint8_t* pb = bsrc + (size_t)(2 * s) * PLANE;
        cp_async_16(sb,                 pa);
        cp_async_16(sb + 4096,          pa + PLANE);
        cp_async_16(sb + 8192,          pb);
        cp_async_16(sb + 8192 + 4096,   pb + 4096);
        cp_async_16(sb + 16384,         pb + PLANE);
        cp_async_16(sb + 16384 + 4096,  pb + PLANE + 4096);
        cp_commit();
    }

    for (int it = 0; it < NIT; it++) {
        cp_wait2();
        __syncthreads();
        int s = it + 3;
        if (s < NIT) {
            uint32_t sb = wdst + (uint32_t)((s & 3) * STAGE);
            const uint8_t* pa = asrc + (size_t)(2 * s) * PLANE;
            const uint8_t* pb = bsrc + (size_t)(2 * s) * PLANE;
            cp_async_16(sb,                 pa);
            cp_async_16(sb + 4096,          pa + PLANE);
            cp_async_16(sb + 8192,          pb);
            cp_async_16(sb + 8192 + 4096,   pb + 4096);
            cp_async_16(sb + 16384,         pb + PLANE);
            cp_async_16(sb + 16384 + 4096,  pb + PLANE + 4096);
        }
        cp_commit();

        uint32_t soff = (uint32_t)((it & 3) * STAGE);
        uint32_t a0 = a_rd + soff;
        uint32_t b0 = b_rd + soff;
        #pragma unroll
        for (int ks = 0; ks < 2; ks++) {
            uint32_t af[4][4], bf[8][2];
            #pragma unroll
            for (int mt = 0; mt < 4; mt++) {
                lds64(af[mt][0], af[mt][2], a0 + (uint32_t)(ks * 4096 + mt * 512));
                lds64(af[mt][1], af[mt][3], a0 + (uint32_t)(ks * 4096 + mt * 512 + 256));
            }
            #pragma unroll
            for (int nt = 0; nt < 8; nt++)
                lds64(bf[nt][0], bf[nt][1], b0 + (uint32_t)(ks * 8192 + nt * 256));
            #pragma unroll
            for (int mt = 0; mt < 4; mt++)
                #pragma unroll
                for (int nt = 0; nt < 8; nt++)
                    mma_e4m3_h(acc[mt][nt][0], acc[mt][nt][1],
                               af[mt][0], af[mt][1], af[mt][2], af[mt][3],
                               bf[nt][0], bf[nt][1]);
        }
    }

    // ---- epilogue: unpack f16 acc, exp + row sums (ib) and col sums (jb) ----
    float colacc[8][2];
    #pragma unroll
    for (int nt = 0; nt < 8; nt++) { colacc[nt][0] = 0.f; colacc[nt][1] = 0.f; }

    #pragma unroll
    for (int mt = 0; mt < 4; mt++) {
        float r0acc = 0.f, r1acc = 0.f;
        int lr0 = wm * 64 + mt * 16 + (lane >> 2);
        int lr1 = lr0 + 8;
        int gr0 = ib * TMR + lr0;
        int gr1 = ib * TMR + lr1;
        #pragma unroll
        for (int nt = 0; nt < 8; nt++) {
            int lc0 = wn * 64 + nt * 8 + (lane & 3) * 2;
            int lc1 = lc0 + 1;
            int gc0 = jb * TNC + lc0;
            int gc1 = gc0 + 1;
            float2 p01 = __half22float2(*(const __half2*)&acc[mt][nt][0]);
            float2 p23 = __half22float2(*(const __half2*)&acc[mt][nt][1]);
            float a00 = p01.x, a01 = p01.y, a10 = p23.x, a11 = p23.y;
            if (posband) {   // pos logits: gc == gr + 4096
                if (gc0 == gr0 + 4096) { float p = a00 * SCALE; g_pos[gr0] = p; g_pos[gc0] = p; }
                if (gc1 == gr0 + 4096) { float p = a01 * SCALE; g_pos[gr0] = p; g_pos[gc1] = p; }
                if (gc0 == gr1 + 4096) { float p = a10 * SCALE; g_pos[gr1] = p; g_pos[gc0] = p; }
                if (gc1 == gr1 + 4096) { float p = a11 * SCALE; g_pos[gr1] = p; g_pos[gc1] = p; }
            }
            float e00 = __expf(a00 * SCALE);
            float e01 = __expf(a01 * SCALE);
            float e10 = __expf(a10 * SCALE);
            float e11 = __expf(a11 * SCALE);
            if (band) {      // keep only gc > gr (dedup + diagonal mask)
                if (gc0 <= gr0) e00 = 0.f;
                if (gc1 <= gr0) e01 = 0.f;
                if (gc0 <= gr1) e10 = 0.f;
                if (gc1 <= gr1) e11 = 0.f;
            }
            r0acc += e00 + e01;
            r1acc += e10 + e11;
            colacc[nt][0] += e00 + e10;
            colacc[nt][1] += e01 + e11;
        }
        r0acc += __shfl_xor_sync(0xffffffffu, r0acc, 1);
        r0acc += __shfl_xor_sync(0xffffffffu, r0acc, 2);
        r1acc += __shfl_xor_sync(0xffffffffu, r1acc, 1);
        r1acc += __shfl_xor_sync(0xffffffffu, r1acc, 2);
        if ((lane & 3) == 0) {
            atomicAdd(&s_row[lr0], r0acc);
            atomicAdd(&s_row[lr1], r1acc);
        }
    }
    #pragma unroll
    for (int nt = 0; nt < 8; nt++) {
        #pragma unroll
        for (int h = 0; h < 2; h++) {
            float v = colacc[nt][h];
            v += __shfl_xor_sync(0xffffffffu, v, 4);
            v += __shfl_xor_sync(0xffffffffu, v, 8);
            v += __shfl_xor_sync(0xffffffffu, v, 16);
            if (lane < 4) atomicAdd(&s_col[wn * 64 + nt * 8 + lane * 2 + h], v);
        }
    }
    __syncthreads();

    if (tid < TMR) atomicAdd(&g_rowsum[ib * TMR + tid], s_row[tid]);
    atomicAdd(&g_rowsum[jb * TNC + tid], s_col[tid]);
}

// ---------------- kernel 3: final mean (out zeroed by norm_kernel) ----------------
__global__ __launch_bounds__(1024) void final_kernel(float* __restrict__ out) {
    int i = blockIdx.x * 1024 + threadIdx.x;
    float s = __logf(g_rowsum[i]) - g_pos[i];
    #pragma unroll
    for (int o = 16; o; o >>= 1) s += __shfl_xor_sync(0xffffffffu, s, o);
    __shared__ float red[32];
    if ((threadIdx.x & 31) == 0) red[threadIdx.x >> 5] = s;
    __syncthreads();
    if (threadIdx.x < 32) {
        float v = red[threadIdx.x];
        #pragma unroll
        for (int o = 16; o; o >>= 1) v += __shfl_xor_sync(0xffffffffu, v, o);
        if (threadIdx.x == 0) atomicAdd(out, v / (float)NROWS);
    }
}

// ---------------- launch ----------------
extern "C" void kernel_launch(void* const* d_in, const int* in_sizes, int n_in,
                              void* d_out, int out_size) {
    (void)in_sizes; (void)n_in; (void)out_size;
    const float* z = (const float*)d_in[0];
    float* out = (float*)d_out;

    cudaFuncSetAttribute(gram_kernel, cudaFuncAttributeMaxDynamicSharedMemorySize, SMEM_DYN);

    norm_kernel<<<NROWS / 8, 256>>>(z, out);
    gram_kernel<<<NTILES, 256, SMEM_DYN>>>();
    final_kernel<<<NROWS / 1024, 1024>>>(out);
}

// round 14
// speedup vs baseline: 1.0811x; 1.0811x over previous
#include <cuda_runtime.h>
#include <cuda_bf16.h>
#include <cuda_fp16.h>
#include <cstdint>
#include <math.h>

#define NROWS 8192
#define DDIM  1024
#define TM    128
#define NTB   (NROWS / TM)            // 64 row-blocks
#define NTILES (NTB * (NTB + 1) / 2)  // 2080 triangular tiles
#define NKT   (DDIM / 32)             // 32 k-slices of 32
#define NIT   (NKT / 2)               // 16 mainloop iterations (BK=64)
#define PLANE ((size_t)NROWS * 32)    // bytes per k-slice plane
#define F8SCALE 16.0f
#define SCALE (14.285714285714285f / (F8SCALE * F8SCALE))

#define STAGE  16384
#define SMEM_DYN (4 * STAGE)          // 65536

// ---------------- device scratch ----------------
__device__ uint8_t g_p8[(size_t)NKT * PLANE];
__device__ float g_rowsum[NROWS];
__device__ float g_pos[NROWS];

// ---------------- PTX helpers ----------------
__device__ __forceinline__ uint32_t smem_u32(const void* p) {
    return (uint32_t)__cvta_generic_to_shared(p);
}
__device__ __forceinline__ void cp_async_16(uint32_t dst, const void* src) {
    asm volatile("cp.async.cg.shared.global [%0], [%1], 16;" :: "r"(dst), "l"(src) : "memory");
}
__device__ __forceinline__ void cp_commit() {
    asm volatile("cp.async.commit_group;" ::: "memory");
}
__device__ __forceinline__ void cp_wait2() {
    asm volatile("cp.async.wait_group 2;" ::: "memory");
}
__device__ __forceinline__ void lds64(uint32_t& r0, uint32_t& r1, uint32_t addr) {
    asm volatile("ld.shared.v2.u32 {%0,%1}, [%2];" : "=r"(r0), "=r"(r1) : "r"(addr));
}
// fp8 x fp8 -> f16 accumulator (half2 pair)
__device__ __forceinline__ void mma_e4m3_h(uint32_t& d0, uint32_t& d1,
                                           uint32_t a0, uint32_t a1, uint32_t a2, uint32_t a3,
                                           uint32_t b0, uint32_t b1) {
    asm volatile("mma.sync.aligned.m16n8k32.row.col.f16.e4m3.e4m3.f16 "
                 "{%0,%1}, {%2,%3,%4,%5}, {%6,%7}, {%0,%1};"
                 : "+r"(d0), "+r"(d1)
                 : "r"(a0), "r"(a1), "r"(a2), "r"(a3), "r"(b0), "r"(b1));
}
__device__ __forceinline__ uint16_t f2e4m3(float hi, float lo) {
    uint16_t r;
    asm("cvt.rn.satfinite.e4m3x2.f32 %0, %1, %2;" : "=h"(r) : "f"(hi), "f"(lo));
    return r;
}

// ---------------- kernel 1: normalize + pack (warp-per-row, single pass) ----------------
__global__ __launch_bounds__(256) void norm_kernel(const float* __restrict__ z,
                                                   float* __restrict__ out) {
    int warp = (blockIdx.x * 256 + threadIdx.x) >> 5;
    int lane = threadIdx.x & 31;
    int row = warp;
    const float4* zr4 = (const float4*)(z + (size_t)row * DDIM);

    float4 v[8];
    float ss = 0.f;
    #pragma unroll
    for (int i = 0; i < 8; i++) {
        v[i] = zr4[lane + 32 * i];
        ss = fmaf(v[i].x, v[i].x, ss);
        ss = fmaf(v[i].y, v[i].y, ss);
        ss = fmaf(v[i].z, v[i].z, ss);
        ss = fmaf(v[i].w, v[i].w, ss);
    }
    #pragma unroll
    for (int o = 16; o; o >>= 1) ss += __shfl_xor_sync(0xffffffffu, ss, o);
    float nrm = fmaxf(sqrtf(ss), 1e-8f);
    float inv = (1.f / nrm) * F8SCALE;

    int natom = row >> 3, gb = row & 7;
    #pragma unroll
    for (int i = 0; i < 8; i++) {
        int q = lane + 32 * i;
        uint32_t word = (uint32_t)f2e4m3(v[i].y * inv, v[i].x * inv)
                      | ((uint32_t)f2e4m3(v[i].w * inv, v[i].z * inv) << 16);
        int kt = q >> 3, tig = q & 3, half = (q >> 2) & 1;
        size_t boff = (size_t)kt * PLANE + (size_t)natom * 256
                    + (size_t)(gb * 4 + tig) * 8 + (size_t)half * 4;
        *(uint32_t*)(g_p8 + boff) = word;
    }
    if (lane == 0) g_rowsum[row] = 0.f;
    if (blockIdx.x == 0 && threadIdx.x == 0) out[0] = 0.f;
}

// ---------------- kernel 2: fp8 triangular gram (f16 acc), 3 CTAs/SM ----------------
__global__ __launch_bounds__(256, 3) void gram_kernel() {
    extern __shared__ uint8_t dsmem[];
    __shared__ float s_row[TM];
    __shared__ float s_col[TM];

    int tid = threadIdx.x;
    int lane = tid & 31, w = tid >> 5;
    int wm = w >> 2, wn = w & 3;

    uint32_t sbase = smem_u32(dsmem);

    int t = blockIdx.x, ib = 0;
    while (t >= NTB - ib) { t -= NTB - ib; ib++; }
    int jb = ib + t;
    bool diag = (ib == jb);
    bool posband = (jb - ib == NTB / 2);

    if (tid < TM) { s_row[tid] = 0.f; s_col[tid] = 0.f; }

    uint32_t wdst   = sbase + (uint32_t)tid * 16;
    const uint8_t* asrc = g_p8 + (size_t)ib * 4096 + tid * 16;
    const uint8_t* bsrc = g_p8 + (size_t)jb * 4096 + tid * 16;
    uint32_t a_rd = sbase + (uint32_t)((wm * 8) * 256 + lane * 8);
    uint32_t b_rd = sbase + (uint32_t)(8192 + (wn * 4) * 256 + lane * 8);

    uint32_t acc[4][4][2];   // f16x2 accumulators
    #pragma unroll
    for (int mt = 0; mt < 4; mt++)
        #pragma unroll
        for (int nt = 0; nt < 4; nt++) { acc[mt][nt][0] = 0u; acc[mt][nt][1] = 0u; }

    #pragma unroll
    for (int s = 0; s < 3; s++) {
        uint32_t sb = wdst + (uint32_t)(s * STAGE);
        const uint8_t* pa = asrc + (size_t)(2 * s) * PLANE;
        const uint8_t* pb = bsrc + (size_t)(2 * s) * PLANE;
        cp_async_16(sb,                pa);
        cp_async_16(sb + 4096,         pa + PLANE);
        cp_async_16(sb + 8192,         pb);
        cp_async_16(sb + 8192 + 4096,  pb + PLANE);
        cp_commit();
    }

    for (int it = 0; it < NIT; it++) {
        cp_wait2();
        __syncthreads();
        int s = it + 3;
        if (s < NIT) {
            uint32_t sb = wdst + (uint32_t)((s & 3) * STAGE);
            const uint8_t* pa = asrc + (size_t)(2 * s) * PLANE;
            const uint8_t* pb = bsrc + (size_t)(2 * s) * PLANE;
            cp_async_16(sb,                pa);
            cp_async_16(sb + 4096,         pa + PLANE);
            cp_async_16(sb + 8192,         pb);
            cp_async_16(sb + 8192 + 4096,  pb + PLANE);
        }
        cp_commit();

        uint32_t soff = (uint32_t)((it & 3) * STAGE);
        uint32_t a0 = a_rd + soff;
        uint32_t b0 = b_rd + soff;
        #pragma unroll
        for (int ks = 0; ks < 2; ks++) {
            uint32_t af[4][4], bf[4][2];
            #pragma unroll
            for (int mt = 0; mt < 4; mt++) {
                lds64(af[mt][0], af[mt][2], a0 + (uint32_t)(ks * 4096 + mt * 512));
                lds64(af[mt][1], af[mt][3], a0 + (uint32_t)(ks * 4096 + mt * 512 + 256));
            }
            #pragma unroll
            for (int nt = 0; nt < 4; nt++)
                lds64(bf[nt][0], bf[nt][1], b0 + (uint32_t)(ks * 4096 + nt * 256));
            #pragma unroll
            for (int mt = 0; mt < 4; mt++)
                #pragma unroll
                for (int nt = 0; nt < 4; nt++)
                    mma_e4m3_h(acc[mt][nt][0], acc[mt][nt][1],
                               af[mt][0], af[mt][1], af[mt][2], af[mt][3],
                               bf[nt][0], bf[nt][1]);
        }
    }

    // ---- epilogue: unpack f16 acc -> exp/reduce ----
    float colacc[4][2];
    #pragma unroll
    for (int nt = 0; nt < 4; nt++) { colacc[nt][0] = 0.f; colacc[nt][1] = 0.f; }

    #pragma unroll
    for (int mt = 0; mt < 4; mt++) {
        float r0acc = 0.f, r1acc = 0.f;
        int lr0 = wm * 64 + mt * 16 + (lane >> 2);
        int lr1 = lr0 + 8;
        #pragma unroll
        for (int nt = 0; nt < 4; nt++) {
            int lc0 = wn * 32 + nt * 8 + (lane & 3) * 2;
            int lc1 = lc0 + 1;
            float2 p01 = __half22float2(*(const __half2*)&acc[mt][nt][0]);
            float2 p23 = __half22float2(*(const __half2*)&acc[mt][nt][1]);
            float a00 = p01.x, a01 = p01.y, a10 = p23.x, a11 = p23.y;
            if (posband) {
                if (lr0 == lc0) { float p = a00 * SCALE; g_pos[ib * TM + lr0] = p; g_pos[jb * TM + lc0] = p; }
                if (lr0 == lc1) { float p = a01 * SCALE; g_pos[ib * TM + lr0] = p; g_pos[jb * TM + lc1] = p; }
                if (lr1 == lc0) { float p = a10 * SCALE; g_pos[ib * TM + lr1] = p; g_pos[jb * TM + lc0] = p; }
                if (lr1 == lc1) { float p = a11 * SCALE; g_pos[ib * TM + lr1] = p; g_pos[jb * TM + lc1] = p; }
            }
            float e00 = __expf(a00 * SCALE);
            float e01 = __expf(a01 * SCALE);
            float e10 = __expf(a10 * SCALE);
            float e11 = __expf(a11 * SCALE);
            if (diag) {
                if (lr0 == lc0) e00 = 0.f;
                if (lr0 == lc1) e01 = 0.f;
                if (lr1 == lc0) e10 = 0.f;
                if (lr1 == lc1) e11 = 0.f;
            }
            r0acc += e00 + e01;
            r1acc += e10 + e11;
            colacc[nt][0] += e00 + e10;
            colacc[nt][1] += e01 + e11;
        }
        r0acc += __shfl_xor_sync(0xffffffffu, r0acc, 1);
        r0acc += __shfl_xor_sync(0xffffffffu, r0acc, 2);
        r1acc += __shfl_xor_sync(0xffffffffu, r1acc, 1);
        r1acc += __shfl_xor_sync(0xffffffffu, r1acc, 2);
        if ((lane & 3) == 0) {
            atomicAdd(&s_row[lr0], r0acc);
            atomicAdd(&s_row[lr1], r1acc);
        }
    }
    if (!diag) {
        #pragma unroll
        for (int nt = 0; nt < 4; nt++) {
            #pragma unroll
            for (int h = 0; h < 2; h++) {
                float v = colacc[nt][h];
                v += __shfl_xor_sync(0xffffffffu, v, 4);
                v += __shfl_xor_sync(0xffffffffu, v, 8);
                v += __shfl_xor_sync(0xffffffffu, v, 16);
                if (lane < 4) atomicAdd(&s_col[wn * 32 + nt * 8 + lane * 2 + h], v);
            }
        }
    }
    __syncthreads();

    if (tid < TM)
        atomicAdd(&g_rowsum[ib * TM + tid], s_row[tid]);
    else if (!diag)
        atomicAdd(&g_rowsum[jb * TM + (tid - TM)], s_col[tid - TM]);
}

// ---------------- kernel 3: final mean (out zeroed by norm_kernel) ----------------
__global__ __launch_bounds__(1024) void final_kernel(float* __restrict__ out) {
    int i = blockIdx.x * 1024 + threadIdx.x;
    float s = __logf(g_rowsum[i]) - g_pos[i];
    #pragma unroll
    for (int o = 16; o; o >>= 1) s += __shfl_xor_sync(0xffffffffu, s, o);
    __shared__ float red[32];
    if ((threadIdx.x & 31) == 0) red[threadIdx.x >> 5] = s;
    __syncthreads();
    if (threadIdx.x < 32) {
        float v = red[threadIdx.x];
        #pragma unroll
        for (int o = 16; o; o >>= 1) v += __shfl_xor_sync(0xffffffffu, v, o);
        if (threadIdx.x == 0) atomicAdd(out, v / (float)NROWS);
    }
}

// ---------------- launch ----------------
extern "C" void kernel_launch(void* const* d_in, const int* in_sizes, int n_in,
                              void* d_out, int out_size) {
    (void)in_sizes; (void)n_in; (void)out_size;
    const float* z = (const float*)d_in[0];
    float* out = (float*)d_out;

    cudaFuncSetAttribute(gram_kernel, cudaFuncAttributeMaxDynamicSharedMemorySize, SMEM_DYN);

    norm_kernel<<<NROWS / 8, 256>>>(z, out);
    gram_kernel<<<NTILES, 256, SMEM_DYN>>>();
    final_kernel<<<NROWS / 1024, 1024>>>(out);
}